// round 1
// baseline (speedup 1.0000x reference)
#include <cuda_runtime.h>
#include <math.h>

#define TT    2048
#define HHD   2048
#define NHEADS 16
#define NKVH   4
#define HDIM   128
#define QSZ    2048
#define KVSZ   512
#define QKVN   3072
#define NEXP   8
#define II     4096
#define EPSV   1e-5f

// ---------------- device scratch (static, no allocations) ----------------
__device__ float g_xn  [TT * HHD];    // rmsnorm1 output
__device__ float g_qkv [TT * QKVN];   // qkv (rope+norm applied in place)
__device__ float g_att [TT * QSZ];    // attention output
__device__ float g_x2  [TT * HHD];    // residual after attention
__device__ float g_y   [TT * HHD];    // rmsnorm2 output
__device__ float g_g   [TT * II];     // gate / h buffer
__device__ float g_u   [TT * II];     // up buffer
__device__ int   g_expert[TT];
__device__ float g_gate  [TT];
__device__ int   g_cnt[NEXP];
__device__ int   g_off[NEXP];
__device__ int   g_cur[NEXP];
__device__ int   g_perm[TT];

// ---------------- rmsnorm ----------------
__global__ __launch_bounds__(256) void rmsnorm_kernel(
    const float* __restrict__ x, const float* __restrict__ w, float* __restrict__ o)
{
    int t = blockIdx.x, tid = threadIdx.x;
    const float* r = x + (size_t)t * HHD;
    float ss = 0.f;
    for (int j = tid; j < HHD; j += 256) { float v = r[j]; ss += v * v; }
    __shared__ float red[256];
    red[tid] = ss; __syncthreads();
    for (int s = 128; s > 0; s >>= 1) { if (tid < s) red[tid] += red[tid + s]; __syncthreads(); }
    float scale = rsqrtf(red[0] / (float)HHD + EPSV);
    float* out = o + (size_t)t * HHD;
    for (int j = tid; j < HHD; j += 256) out[j] = r[j] * scale * w[j];
}

// ---------------- generic fp32 tiled GEMM: C = A(MxK) * B(KxN) [+ Res] ----------------
__global__ __launch_bounds__(256) void gemm_kernel(
    const float* __restrict__ A, const float* __restrict__ B,
    float* __restrict__ C, int M, int N, int K, const float* __restrict__ Res)
{
    __shared__ float As[16][64];
    __shared__ float Bs[16][64];
    int bm = blockIdx.y * 64, bn = blockIdx.x * 64;
    int tid = threadIdx.x;
    int ar = tid >> 2, ac = (tid & 3) << 2;     // A: 64 rows x 16 cols, one float4/thread
    int br = tid >> 4, bc = (tid & 15) << 2;    // B: 16 rows x 64 cols
    int ty = tid >> 4, tx = tid & 15;
    float acc[4][4] = {};
    const float* Aptr = A + (size_t)(bm + ar) * K + ac;
    const float* Bptr = B + (size_t)br * N + bn + bc;
    for (int k0 = 0; k0 < K; k0 += 16) {
        float4 av = *(const float4*)(Aptr + k0);
        As[ac + 0][ar] = av.x; As[ac + 1][ar] = av.y;
        As[ac + 2][ar] = av.z; As[ac + 3][ar] = av.w;
        *(float4*)&Bs[br][bc] = *(const float4*)(Bptr + (size_t)k0 * N);
        __syncthreads();
#pragma unroll
        for (int k = 0; k < 16; k++) {
            float4 a = *(float4*)&As[k][ty << 2];
            float4 b = *(float4*)&Bs[k][tx << 2];
            acc[0][0] += a.x * b.x; acc[0][1] += a.x * b.y; acc[0][2] += a.x * b.z; acc[0][3] += a.x * b.w;
            acc[1][0] += a.y * b.x; acc[1][1] += a.y * b.y; acc[1][2] += a.y * b.z; acc[1][3] += a.y * b.w;
            acc[2][0] += a.z * b.x; acc[2][1] += a.z * b.y; acc[2][2] += a.z * b.z; acc[2][3] += a.z * b.w;
            acc[3][0] += a.w * b.x; acc[3][1] += a.w * b.y; acc[3][2] += a.w * b.z; acc[3][3] += a.w * b.w;
        }
        __syncthreads();
    }
#pragma unroll
    for (int i = 0; i < 4; i++) {
        size_t row = bm + (ty << 2) + i;
        float4 v = make_float4(acc[i][0], acc[i][1], acc[i][2], acc[i][3]);
        size_t idx = row * N + bn + (tx << 2);
        if (Res) { float4 r4 = *(const float4*)&Res[idx];
                   v.x += r4.x; v.y += r4.y; v.z += r4.z; v.w += r4.w; }
        *(float4*)&C[idx] = v;
    }
}

// ---------------- rope + q/k rmsnorm (in place on qkv) ----------------
__global__ __launch_bounds__(256) void ropenorm_kernel(
    float* __restrict__ qkv, const int* __restrict__ pos,
    const float* __restrict__ qw, const float* __restrict__ kw)
{
    int t = blockIdx.x, tid = threadIdx.x;
    float* row = qkv + (size_t)t * QKVN;
    float p = (float)pos[t];
    const float lgt = logf(500000.0f);
    __shared__ float red[256];
    __shared__ float sq, sk;

    // Q: 16 heads * 64 pairs = 1024 pairs
    float ss = 0.f;
    for (int idx = tid; idx < 1024; idx += 256) {
        int hh = idx >> 6, i = idx & 63;
        float inv = expf(-lgt * (float)i * (1.0f / 64.0f));
        float fr = p * inv, c = cosf(fr), s = sinf(fr);
        float x1 = row[hh * 128 + i], x2 = row[hh * 128 + 64 + i];
        float o1 = x1 * c - x2 * s, o2 = x2 * c + x1 * s;
        row[hh * 128 + i] = o1; row[hh * 128 + 64 + i] = o2;
        ss += o1 * o1 + o2 * o2;
    }
    red[tid] = ss; __syncthreads();
    for (int s2 = 128; s2 > 0; s2 >>= 1) { if (tid < s2) red[tid] += red[tid + s2]; __syncthreads(); }
    if (tid == 0) sq = rsqrtf(red[0] / (float)QSZ + EPSV);
    __syncthreads();

    // K: 4 heads * 64 pairs = 256 pairs
    float ssk = 0.f;
    {
        int hh = tid >> 6, i = tid & 63;
        float inv = expf(-lgt * (float)i * (1.0f / 64.0f));
        float fr = p * inv, c = cosf(fr), s = sinf(fr);
        float* kbase = row + QSZ;
        float x1 = kbase[hh * 128 + i], x2 = kbase[hh * 128 + 64 + i];
        float o1 = x1 * c - x2 * s, o2 = x2 * c + x1 * s;
        kbase[hh * 128 + i] = o1; kbase[hh * 128 + 64 + i] = o2;
        ssk = o1 * o1 + o2 * o2;
    }
    red[tid] = ssk; __syncthreads();
    for (int s2 = 128; s2 > 0; s2 >>= 1) { if (tid < s2) red[tid] += red[tid + s2]; __syncthreads(); }
    if (tid == 0) sk = rsqrtf(red[0] / (float)KVSZ + EPSV);
    __syncthreads();

    for (int j = tid; j < QSZ; j += 256) row[j] *= sq * qw[j];
    for (int j = tid; j < KVSZ; j += 256) row[QSZ + j] *= sk * kw[j];
}

// ---------------- flash attention (fp32, causal, GQA 16q/4kv) ----------------
#define QKSTR 132   // padded row stride for 128-dim tiles
#define SMEM_ATTN ((3 * 64 * QKSTR + 64 * 64) * 4)

__global__ __launch_bounds__(256) void attn_kernel(
    const float* __restrict__ qkv, float* __restrict__ O)
{
    extern __shared__ float sh[];
    float* Qs = sh;
    float* Ks = sh + 64 * QKSTR;
    float* Vs = sh + 2 * 64 * QKSTR;
    float* Ps = sh + 3 * 64 * QKSTR;

    int m0 = blockIdx.x * 64;
    int h  = blockIdx.y;
    int kvh = h >> 2;
    int tid = threadIdx.x, lane = tid & 31, w = tid >> 5;
    const float scl = 0.08838834764831845f;

    for (int i = tid; i < 2048; i += 256) {
        int r = i >> 5, c = (i & 31) << 2;
        *(float4*)&Qs[r * QKSTR + c] =
            *(const float4*)&qkv[(size_t)(m0 + r) * QKVN + h * HDIM + c];
    }

    float mrow[8], lrow[8], oacc[8][4];
#pragma unroll
    for (int r = 0; r < 8; r++) {
        mrow[r] = -1e30f; lrow[r] = 0.f;
        oacc[r][0] = oacc[r][1] = oacc[r][2] = oacc[r][3] = 0.f;
    }
    int d0 = lane << 2;

    for (int n0 = 0; n0 <= m0; n0 += 64) {
        __syncthreads();
        for (int i = tid; i < 2048; i += 256) {
            int r = i >> 5, c = (i & 31) << 2;
            *(float4*)&Ks[r * QKSTR + c] =
                *(const float4*)&qkv[(size_t)(n0 + r) * QKVN + QSZ + kvh * HDIM + c];
            *(float4*)&Vs[r * QKSTR + c] =
                *(const float4*)&qkv[(size_t)(n0 + r) * QKVN + QSZ + KVSZ + kvh * HDIM + c];
        }
        __syncthreads();

        // S = Q Kᵀ  (warp w owns rows 8w..8w+7; lane owns cols lane, lane+32)
        float s0[8] = {0.f,0.f,0.f,0.f,0.f,0.f,0.f,0.f};
        float s1[8] = {0.f,0.f,0.f,0.f,0.f,0.f,0.f,0.f};
        for (int k = 0; k < 128; k++) {
            float k0 = Ks[lane * QKSTR + k];
            float k1 = Ks[(lane + 32) * QKSTR + k];
#pragma unroll
            for (int r = 0; r < 8; r++) {
                float q = Qs[(w * 8 + r) * QKSTR + k];
                s0[r] += q * k0; s1[r] += q * k1;
            }
        }
        bool diag = (n0 + 63 > m0);  // tile touches the diagonal
#pragma unroll
        for (int r = 0; r < 8; r++) {
            int grow = m0 + w * 8 + r;
            float v0 = s0[r] * scl, v1 = s1[r] * scl;
            if (diag) {
                if (n0 + lane      > grow) v0 = -1e30f;
                if (n0 + lane + 32 > grow) v1 = -1e30f;
            }
            float tmax = fmaxf(v0, v1);
#pragma unroll
            for (int o = 16; o; o >>= 1) tmax = fmaxf(tmax, __shfl_xor_sync(~0u, tmax, o));
            float nm = fmaxf(mrow[r], tmax);
            float p0 = __expf(v0 - nm), p1 = __expf(v1 - nm);
            float corr = __expf(mrow[r] - nm);
            float psum = p0 + p1;
#pragma unroll
            for (int o = 16; o; o >>= 1) psum += __shfl_xor_sync(~0u, psum, o);
            lrow[r] = lrow[r] * corr + psum;
            mrow[r] = nm;
            oacc[r][0] *= corr; oacc[r][1] *= corr; oacc[r][2] *= corr; oacc[r][3] *= corr;
            Ps[(w * 8 + r) * 64 + lane]      = p0;
            Ps[(w * 8 + r) * 64 + lane + 32] = p1;
        }
        __syncwarp();
        for (int n = 0; n < 64; n++) {
            float4 v = *(float4*)&Vs[n * QKSTR + d0];
#pragma unroll
            for (int r = 0; r < 8; r++) {
                float p = Ps[(w * 8 + r) * 64 + n];
                oacc[r][0] += p * v.x; oacc[r][1] += p * v.y;
                oacc[r][2] += p * v.z; oacc[r][3] += p * v.w;
            }
        }
    }
#pragma unroll
    for (int r = 0; r < 8; r++) {
        float inv = 1.0f / lrow[r];
        float4 o = make_float4(oacc[r][0] * inv, oacc[r][1] * inv,
                               oacc[r][2] * inv, oacc[r][3] * inv);
        *(float4*)&O[(size_t)(m0 + w * 8 + r) * QSZ + h * HDIM + d0] = o;
    }
}

// ---------------- router / permutation ----------------
__global__ void zero_kernel()
{
    int i = threadIdx.x;
    if (i < NEXP) { g_cnt[i] = 0; g_cur[i] = 0; }
}

__global__ __launch_bounds__(256) void router_kernel(
    const float* __restrict__ y, const float* __restrict__ rw)
{
    int t = blockIdx.x, tid = threadIdx.x;
    const float* x = y + (size_t)t * HHD;
    float part[NEXP] = {};
    for (int k = tid; k < HHD; k += 256) {
        float xv = x[k];
        const float* r = rw + (size_t)k * NEXP;
#pragma unroll
        for (int e = 0; e < NEXP; e++) part[e] += xv * r[e];
    }
    __shared__ float red[256];
    __shared__ float logit[NEXP];
    for (int e = 0; e < NEXP; e++) {
        red[tid] = part[e]; __syncthreads();
        for (int s = 128; s > 0; s >>= 1) { if (tid < s) red[tid] += red[tid + s]; __syncthreads(); }
        if (tid == 0) logit[e] = red[0];
        __syncthreads();
    }
    if (tid == 0) {
        int am = 0; float mv = logit[0];
        for (int e = 1; e < NEXP; e++) if (logit[e] > mv) { mv = logit[e]; am = e; }
        g_expert[t] = am;
        g_gate[t]   = 1.0f / (1.0f + expf(-mv));
        atomicAdd(&g_cnt[am], 1);
    }
}

__global__ void scan_kernel()
{
    int s = 0;
    for (int e = 0; e < NEXP; e++) { g_off[e] = s; s += g_cnt[e]; }
}

__global__ void scatter_kernel()
{
    int t = blockIdx.x * 256 + threadIdx.x;
    if (t >= TT) return;
    int e = g_expert[t];
    int p = atomicAdd(&g_cur[e], 1);
    g_perm[g_off[e] + p] = t;
}

// ---------------- silu(g) * u -> g ----------------
__global__ __launch_bounds__(256) void silu_kernel(float* __restrict__ g, const float* __restrict__ u)
{
    int i = blockIdx.x * 256 + threadIdx.x;
    float x = g[i];
    g[i] = (x / (1.0f + __expf(-x))) * u[i];
}

// ---------------- grouped GEMM (gate/up): Cg[grouped] = Y[perm] * W[e] ----------------
__global__ __launch_bounds__(256) void gemm_grouped_gu(
    const float* __restrict__ Y, const float* __restrict__ W,
    float* __restrict__ Cg, int N, int K)
{
    int e = blockIdx.z;
    int cnt = g_cnt[e];
    int r0 = blockIdx.y * 64;
    if (r0 >= cnt) return;
    int base = g_off[e];
    const float* B = W + (size_t)e * K * N;

    __shared__ float As[16][64];
    __shared__ float Bs[16][64];
    int bn = blockIdx.x * 64;
    int tid = threadIdx.x;
    int ar = tid >> 2, ac = (tid & 3) << 2;
    int br = tid >> 4, bc = (tid & 15) << 2;
    int ty = tid >> 4, tx = tid & 15;
    float acc[4][4] = {};
    int rr = r0 + ar; if (rr >= cnt) rr = cnt - 1;
    int token = g_perm[base + rr];
    const float* Aptr = Y + (size_t)token * K + ac;
    const float* Bptr = B + (size_t)br * N + bn + bc;
    for (int k0 = 0; k0 < K; k0 += 16) {
        float4 av = *(const float4*)(Aptr + k0);
        As[ac + 0][ar] = av.x; As[ac + 1][ar] = av.y;
        As[ac + 2][ar] = av.z; As[ac + 3][ar] = av.w;
        *(float4*)&Bs[br][bc] = *(const float4*)(Bptr + (size_t)k0 * N);
        __syncthreads();
#pragma unroll
        for (int k = 0; k < 16; k++) {
            float4 a = *(float4*)&As[k][ty << 2];
            float4 b = *(float4*)&Bs[k][tx << 2];
            acc[0][0] += a.x * b.x; acc[0][1] += a.x * b.y; acc[0][2] += a.x * b.z; acc[0][3] += a.x * b.w;
            acc[1][0] += a.y * b.x; acc[1][1] += a.y * b.y; acc[1][2] += a.y * b.z; acc[1][3] += a.y * b.w;
            acc[2][0] += a.z * b.x; acc[2][1] += a.z * b.y; acc[2][2] += a.z * b.z; acc[2][3] += a.z * b.w;
            acc[3][0] += a.w * b.x; acc[3][1] += a.w * b.y; acc[3][2] += a.w * b.z; acc[3][3] += a.w * b.w;
        }
        __syncthreads();
    }
#pragma unroll
    for (int i = 0; i < 4; i++) {
        int rloc = (ty << 2) + i;
        if (r0 + rloc < cnt) {
            size_t grow = base + r0 + rloc;
            float4 v = make_float4(acc[i][0], acc[i][1], acc[i][2], acc[i][3]);
            *(float4*)&Cg[grow * N + bn + (tx << 2)] = v;
        }
    }
}

// ---------------- grouped GEMM down: out[tok] += gate[tok] * (Hg * Wd[e]) ----------------
__global__ __launch_bounds__(256) void gemm_grouped_down(
    const float* __restrict__ Hg, const float* __restrict__ Wd,
    float* __restrict__ Out, int N, int K)
{
    int e = blockIdx.z;
    int cnt = g_cnt[e];
    int r0 = blockIdx.y * 64;
    if (r0 >= cnt) return;
    int base = g_off[e];
    const float* B = Wd + (size_t)e * K * N;

    __shared__ float As[16][64];
    __shared__ float Bs[16][64];
    int bn = blockIdx.x * 64;
    int tid = threadIdx.x;
    int ar = tid >> 2, ac = (tid & 3) << 2;
    int br = tid >> 4, bc = (tid & 15) << 2;
    int ty = tid >> 4, tx = tid & 15;
    float acc[4][4] = {};
    int arow = base + r0 + ar; if (arow > TT - 1) arow = TT - 1;
    const float* Aptr = Hg + (size_t)arow * K + ac;
    const float* Bptr = B + (size_t)br * N + bn + bc;
    for (int k0 = 0; k0 < K; k0 += 16) {
        float4 av = *(const float4*)(Aptr + k0);
        As[ac + 0][ar] = av.x; As[ac + 1][ar] = av.y;
        As[ac + 2][ar] = av.z; As[ac + 3][ar] = av.w;
        *(float4*)&Bs[br][bc] = *(const float4*)(Bptr + (size_t)k0 * N);
        __syncthreads();
#pragma unroll
        for (int k = 0; k < 16; k++) {
            float4 a = *(float4*)&As[k][ty << 2];
            float4 b = *(float4*)&Bs[k][tx << 2];
            acc[0][0] += a.x * b.x; acc[0][1] += a.x * b.y; acc[0][2] += a.x * b.z; acc[0][3] += a.x * b.w;
            acc[1][0] += a.y * b.x; acc[1][1] += a.y * b.y; acc[1][2] += a.y * b.z; acc[1][3] += a.y * b.w;
            acc[2][0] += a.z * b.x; acc[2][1] += a.z * b.y; acc[2][2] += a.z * b.z; acc[2][3] += a.z * b.w;
            acc[3][0] += a.w * b.x; acc[3][1] += a.w * b.y; acc[3][2] += a.w * b.z; acc[3][3] += a.w * b.w;
        }
        __syncthreads();
    }
#pragma unroll
    for (int i = 0; i < 4; i++) {
        int rloc = (ty << 2) + i;
        if (r0 + rloc < cnt) {
            int tok = g_perm[base + r0 + rloc];
            float gt = g_gate[tok];
            size_t idx = (size_t)tok * N + bn + (tx << 2);
            float4 o = *(float4*)&Out[idx];
            o.x += gt * acc[i][0]; o.y += gt * acc[i][1];
            o.z += gt * acc[i][2]; o.w += gt * acc[i][3];
            *(float4*)&Out[idx] = o;
        }
    }
}

// ---------------- launcher ----------------
extern "C" void kernel_launch(void* const* d_in, const int* in_sizes, int n_in,
                              void* d_out, int out_size)
{
    const int*   positions = (const int*)  d_in[0];
    const float* hidden    = (const float*)d_in[1];
    const float* ln1       = (const float*)d_in[2];
    const float* ln2       = (const float*)d_in[3];
    const float* w_qkv     = (const float*)d_in[4];
    const float* w_o       = (const float*)d_in[5];
    const float* qnw       = (const float*)d_in[6];
    const float* knw       = (const float*)d_in[7];
    const float* rw        = (const float*)d_in[8];
    const float* wsg       = (const float*)d_in[9];
    const float* wsu       = (const float*)d_in[10];
    const float* wsd       = (const float*)d_in[11];
    const float* weg       = (const float*)d_in[12];
    const float* weu       = (const float*)d_in[13];
    const float* wed       = (const float*)d_in[14];
    float* out = (float*)d_out;

    void* p;
    cudaGetSymbolAddress(&p, g_xn);  float* xn  = (float*)p;
    cudaGetSymbolAddress(&p, g_qkv); float* qkv = (float*)p;
    cudaGetSymbolAddress(&p, g_att); float* att = (float*)p;
    cudaGetSymbolAddress(&p, g_x2);  float* x2  = (float*)p;
    cudaGetSymbolAddress(&p, g_y);   float* y   = (float*)p;
    cudaGetSymbolAddress(&p, g_g);   float* gg  = (float*)p;
    cudaGetSymbolAddress(&p, g_u);   float* uu  = (float*)p;

    cudaFuncSetAttribute(attn_kernel, cudaFuncAttributeMaxDynamicSharedMemorySize, SMEM_ATTN);

    // 1. x = rmsnorm(hidden, ln1)
    rmsnorm_kernel<<<TT, 256>>>(hidden, ln1, xn);
    // 2. qkv = x @ w_qkv
    gemm_kernel<<<dim3(QKVN / 64, TT / 64), 256>>>(xn, w_qkv, qkv, TT, QKVN, HHD, nullptr);
    // 3. rope + q/k rmsnorm in place
    ropenorm_kernel<<<TT, 256>>>(qkv, positions, qnw, knw);
    // 4. flash attention
    attn_kernel<<<dim3(TT / 64, NHEADS), 256, SMEM_ATTN>>>(qkv, att);
    // 5. x2 = hidden + attn @ w_o
    gemm_kernel<<<dim3(HHD / 64, TT / 64), 256>>>(att, w_o, x2, TT, HHD, QSZ, hidden);
    // 6. y = rmsnorm(x2, ln2)
    rmsnorm_kernel<<<TT, 256>>>(x2, ln2, y);
    // 7. router: expert idx + sigmoid gate + counts
    zero_kernel<<<1, 32>>>();
    router_kernel<<<TT, 256>>>(y, rw);
    scan_kernel<<<1, 1>>>();
    scatter_kernel<<<TT / 256, 256>>>();
    // 8. shared expert
    gemm_kernel<<<dim3(II / 64, TT / 64), 256>>>(y, wsg, gg, TT, II, HHD, nullptr);
    gemm_kernel<<<dim3(II / 64, TT / 64), 256>>>(y, wsu, uu, TT, II, HHD, nullptr);
    silu_kernel<<<(TT * II) / 256, 256>>>(gg, uu);
    gemm_kernel<<<dim3(HHD / 64, TT / 64), 256>>>(gg, wsd, out, TT, HHD, II, x2);
    // 9. routed experts (grouped by permutation)
    gemm_grouped_gu<<<dim3(II / 64, TT / 64, NEXP), 256>>>(y, weg, gg, II, HHD);
    gemm_grouped_gu<<<dim3(II / 64, TT / 64, NEXP), 256>>>(y, weu, uu, II, HHD);
    silu_kernel<<<(TT * II) / 256, 256>>>(gg, uu);
    gemm_grouped_down<<<dim3(HHD / 64, TT / 64, NEXP), 256>>>(gg, wed, out, HHD, II);
}